// round 1
// baseline (speedup 1.0000x reference)
#include <cuda_runtime.h>
#include <cstdint>

#define BB 8
#define SS 384
#define IND 512
#define EE 512
#define HH 8
#define DD 64
#define RR 767              // distinct (j-i) offsets: j-i+383 in [0,766]
#define SCALEF 0.07216878364870323f   // 1/sqrt(64*3)

#define QSZ (BB*HH*SS*DD)   // 1,572,864
#define PSZ (HH*RR*DD)      //   392,704
#define LSZ (BB*HH*SS*SS)   // 9,437,184
#define VSZ (BB*SS*EE)      // 1,572,864

__device__ float g_buf[3*QSZ + 2*PSZ + LSZ + VSZ];

// ---------------------------------------------------------------------------
// SGEMM: C[M,N] = A[M,K] @ W[N,K]^T + bias, 128x128 tile, 8x8 per thread.
// MODE 0: plain row-major C (N=512 stride), W0/b0/o0.
// MODE 1: fused QKV, N=1536 (col block selects Wq/Wk/Wv), writes [B,H,S,D].
// MODE 2: pos projection, M=767, writes [H,RR,D].
// ---------------------------------------------------------------------------
template<int MODE>
__launch_bounds__(256)
__global__ void sgemm128(const float* __restrict__ A,
                         const float* __restrict__ W0, const float* __restrict__ W1, const float* __restrict__ W2,
                         const float* __restrict__ b0, const float* __restrict__ b1, const float* __restrict__ b2,
                         float* __restrict__ o0, float* __restrict__ o1, float* __restrict__ o2,
                         int M, int K)
{
    __shared__ float As[8][128];
    __shared__ float Bs[8][128];
    const int tid = threadIdx.x;
    const int m0 = blockIdx.x * 128;
    const int n0 = blockIdx.y * 128;

    const float* W = W0;
    const float* bias = b0;
    int which = 0;
    if (MODE == 1) {
        which = n0 >> 9;
        W    = (which == 0) ? W0 : (which == 1) ? W1 : W2;
        bias = (which == 0) ? b0 : (which == 1) ? b1 : b2;
    }
    const int nW0 = (MODE == 1) ? (n0 & 511) : n0;

    const int lr = tid >> 1;        // 0..127
    const int ls = (tid & 1) * 4;   // 0 or 4
    const int tm = (tid >> 4) * 8;  // thread row base
    const int tn = (tid & 15) * 8;  // thread col base

    float acc[8][8];
#pragma unroll
    for (int i = 0; i < 8; i++)
#pragma unroll
        for (int j = 0; j < 8; j++) acc[i][j] = 0.f;

    for (int k0 = 0; k0 < K; k0 += 8) {
        float4 av = make_float4(0.f, 0.f, 0.f, 0.f);
        if (m0 + lr < M)
            av = *(const float4*)(A + (size_t)(m0 + lr) * K + k0 + ls);
        float4 wv = *(const float4*)(W + (size_t)(nW0 + lr) * K + k0 + ls);
        __syncthreads();
        As[ls + 0][lr] = av.x; As[ls + 1][lr] = av.y; As[ls + 2][lr] = av.z; As[ls + 3][lr] = av.w;
        Bs[ls + 0][lr] = wv.x; Bs[ls + 1][lr] = wv.y; Bs[ls + 2][lr] = wv.z; Bs[ls + 3][lr] = wv.w;
        __syncthreads();
#pragma unroll
        for (int kk = 0; kk < 8; kk++) {
            float a[8], w8[8];
            *(float4*)&a[0]  = *(const float4*)&As[kk][tm];
            *(float4*)&a[4]  = *(const float4*)&As[kk][tm + 4];
            *(float4*)&w8[0] = *(const float4*)&Bs[kk][tn];
            *(float4*)&w8[4] = *(const float4*)&Bs[kk][tn + 4];
#pragma unroll
            for (int i = 0; i < 8; i++)
#pragma unroll
                for (int j = 0; j < 8; j++)
                    acc[i][j] = fmaf(a[i], w8[j], acc[i][j]);
        }
    }

#pragma unroll
    for (int i = 0; i < 8; i++) {
        const int m = m0 + tm + i;
        if (m >= M) break;
#pragma unroll
        for (int j = 0; j < 8; j++) {
            const int n = n0 + tn + j;
            if (MODE == 0) {
                o0[(size_t)m * 512 + n] = acc[i][j] + bias[n];
            } else if (MODE == 1) {
                const int nn = n & 511;
                const float c = acc[i][j] + bias[nn];
                const int h = nn >> 6, d = nn & 63;
                const int b = m / SS, s = m % SS;
                float* o = (which == 0) ? o0 : (which == 1) ? o1 : o2;
                o[(((size_t)(b * HH + h)) * SS + s) * DD + d] = c;
            } else {
                const float c = acc[i][j] + bias[n];
                const int h = n >> 6, d = n & 63;
                o0[((size_t)h * RR + m) * DD + d] = c;
            }
        }
    }
}

// ---------------------------------------------------------------------------
// Fused disentangled logits: per (b,h), 64x64 tile of (i,j).
// logits = (q_i.k_j + q_i.pk[j-i] + pq[j-i].k_j) * SCALE, masked.
// pk/pq diagonal bands (127 rows) staged in smem.
// ---------------------------------------------------------------------------
#define LOGITS_SMEM ((2*64*65 + 2*128*65) * (int)sizeof(float))  // 99,840 B

__launch_bounds__(256)
__global__ void logits_kernel(const float* __restrict__ gq, const float* __restrict__ gk,
                              const float* __restrict__ gpk, const float* __restrict__ gpq,
                              float* __restrict__ glog, const int* __restrict__ mask)
{
    extern __shared__ float sm[];
    float* Qs  = sm;                 // [64][65]
    float* Ks  = Qs + 64 * 65;       // [64][65]
    float* PKs = Ks + 64 * 65;       // [128][65]
    float* PQs = PKs + 128 * 65;     // [128][65]

    const int bh = blockIdx.z;
    const int b = bh >> 3, h = bh & 7;
    const int i0 = blockIdx.x * 64;
    const int j0 = blockIdx.y * 64;
    const int tid = threadIdx.y * 16 + threadIdx.x;

    const float* qbase = gq + ((size_t)bh * SS + i0) * DD;
    const float* kbase = gk + ((size_t)bh * SS + j0) * DD;
    for (int t = tid; t < 64 * 16; t += 256) {
        const int r = t >> 4, c = (t & 15) * 4;
        float4 v = *(const float4*)(qbase + r * DD + c);
        Qs[r * 65 + c] = v.x; Qs[r * 65 + c + 1] = v.y; Qs[r * 65 + c + 2] = v.z; Qs[r * 65 + c + 3] = v.w;
        float4 w = *(const float4*)(kbase + r * DD + c);
        Ks[r * 65 + c] = w.x; Ks[r * 65 + c + 1] = w.y; Ks[r * 65 + c + 2] = w.z; Ks[r * 65 + c + 3] = w.w;
    }
    const int base_r = j0 - i0 + 320;   // band row r -> global rel index base_r + r
    const float* pkb = gpk + (size_t)h * RR * DD;
    const float* pqb = gpq + (size_t)h * RR * DD;
    for (int t = tid; t < 128 * 16; t += 256) {
        const int r = t >> 4, c = (t & 15) * 4;
        float4 v = make_float4(0.f, 0.f, 0.f, 0.f);
        float4 w = make_float4(0.f, 0.f, 0.f, 0.f);
        if (r < 127) {   // base_r + r guaranteed within [0, 766]
            const int rg = base_r + r;
            v = *(const float4*)(pkb + (size_t)rg * DD + c);
            w = *(const float4*)(pqb + (size_t)rg * DD + c);
        }
        PKs[r * 65 + c] = v.x; PKs[r * 65 + c + 1] = v.y; PKs[r * 65 + c + 2] = v.z; PKs[r * 65 + c + 3] = v.w;
        PQs[r * 65 + c] = w.x; PQs[r * 65 + c + 1] = w.y; PQs[r * 65 + c + 2] = w.z; PQs[r * 65 + c + 3] = w.w;
    }
    __syncthreads();

    const int il = threadIdx.y * 4, jl = threadIdx.x * 4;
    const int rb = jl - il + 60;   // band index for (a=3,c=0); (a,c) uses rb + (c - a + 3)
    float acc[4][4];
#pragma unroll
    for (int a = 0; a < 4; a++)
#pragma unroll
        for (int c = 0; c < 4; c++) acc[a][c] = 0.f;

#pragma unroll 4
    for (int d = 0; d < 64; d++) {
        float qv[4], kv[4], pk7[7], pq7[7];
#pragma unroll
        for (int a = 0; a < 4; a++) qv[a] = Qs[(il + a) * 65 + d];
#pragma unroll
        for (int c = 0; c < 4; c++) kv[c] = Ks[(jl + c) * 65 + d];
#pragma unroll
        for (int t = 0; t < 7; t++) {
            pk7[t] = PKs[(rb + t) * 65 + d];
            pq7[t] = PQs[(rb + t) * 65 + d];
        }
#pragma unroll
        for (int a = 0; a < 4; a++)
#pragma unroll
            for (int c = 0; c < 4; c++) {
                const int t = c - a + 3;
                acc[a][c] = fmaf(qv[a], kv[c] + pk7[t], fmaf(pq7[t], kv[c], acc[a][c]));
            }
    }

    float* lb = glog + ((size_t)bh * SS + i0) * SS;
#pragma unroll
    for (int a = 0; a < 4; a++) {
        const int i = il + a;
#pragma unroll
        for (int c = 0; c < 4; c++) {
            const int j = j0 + jl + c;
            float l = acc[a][c] * SCALEF;
            if (mask[b * SS + j] == 0) l = -9.0e15f;
            lb[(size_t)i * SS + j] = l;
        }
    }
}

// ---------------------------------------------------------------------------
// Row softmax over S=384, in place. One block (128 threads) per row.
// ---------------------------------------------------------------------------
__launch_bounds__(128)
__global__ void softmax_kernel(float* __restrict__ glog)
{
    float* p = glog + (size_t)blockIdx.x * SS;
    const int t = threadIdx.x;
    float v0 = p[t], v1 = p[t + 128], v2 = p[t + 256];

    __shared__ float red[4];
    float m = fmaxf(v0, fmaxf(v1, v2));
#pragma unroll
    for (int o = 16; o > 0; o >>= 1) m = fmaxf(m, __shfl_xor_sync(0xffffffffu, m, o));
    if ((t & 31) == 0) red[t >> 5] = m;
    __syncthreads();
    m = fmaxf(fmaxf(red[0], red[1]), fmaxf(red[2], red[3]));

    v0 = __expf(v0 - m); v1 = __expf(v1 - m); v2 = __expf(v2 - m);
    float s = v0 + v1 + v2;
#pragma unroll
    for (int o = 16; o > 0; o >>= 1) s += __shfl_xor_sync(0xffffffffu, s, o);
    __syncthreads();
    if ((t & 31) == 0) red[t >> 5] = s;
    __syncthreads();
    s = red[0] + red[1] + red[2] + red[3];

    const float inv = 1.0f / s;
    p[t] = v0 * inv; p[t + 128] = v1 * inv; p[t + 256] = v2 * inv;
}

// ---------------------------------------------------------------------------
// A@V: per (b,h), attn(384x384) @ v(384x64) -> vals[b][s][h*64+d]  ([B,S,E])
// ---------------------------------------------------------------------------
__launch_bounds__(256)
__global__ void av_kernel(const float* __restrict__ attn_all, const float* __restrict__ gv,
                          float* __restrict__ vals)
{
    __shared__ float As[64][33];
    __shared__ float Vs[32][65];
    const int bh = blockIdx.y;
    const int b = bh >> 3, h = bh & 7;
    const int i0 = blockIdx.x * 64;
    const int tid = threadIdx.y * 16 + threadIdx.x;

    const float* attn = attn_all + ((size_t)bh * SS + i0) * SS;
    const float* vb = gv + (size_t)bh * SS * DD;

    float acc[4][4];
#pragma unroll
    for (int a = 0; a < 4; a++)
#pragma unroll
        for (int c = 0; c < 4; c++) acc[a][c] = 0.f;

    for (int k0 = 0; k0 < SS; k0 += 32) {
        for (int t = tid; t < 64 * 8; t += 256) {
            const int r = t >> 3, c = (t & 7) * 4;
            float4 v = *(const float4*)(attn + (size_t)r * SS + k0 + c);
            As[r][c] = v.x; As[r][c + 1] = v.y; As[r][c + 2] = v.z; As[r][c + 3] = v.w;
        }
        for (int t = tid; t < 32 * 16; t += 256) {
            const int r = t >> 4, c = (t & 15) * 4;
            float4 v = *(const float4*)(vb + (size_t)(k0 + r) * DD + c);
            Vs[r][c] = v.x; Vs[r][c + 1] = v.y; Vs[r][c + 2] = v.z; Vs[r][c + 3] = v.w;
        }
        __syncthreads();
#pragma unroll 8
        for (int kk = 0; kk < 32; kk++) {
            float a4[4], v4[4];
#pragma unroll
            for (int a = 0; a < 4; a++) a4[a] = As[threadIdx.y * 4 + a][kk];
#pragma unroll
            for (int c = 0; c < 4; c++) v4[c] = Vs[kk][threadIdx.x * 4 + c];
#pragma unroll
            for (int a = 0; a < 4; a++)
#pragma unroll
                for (int c = 0; c < 4; c++) acc[a][c] = fmaf(a4[a], v4[c], acc[a][c]);
        }
        __syncthreads();
    }

#pragma unroll
    for (int a = 0; a < 4; a++) {
        const int i = i0 + threadIdx.y * 4 + a;
#pragma unroll
        for (int c = 0; c < 4; c++) {
            const int d = threadIdx.x * 4 + c;
            vals[((size_t)b * SS + i) * EE + h * DD + d] = acc[a][c];
        }
    }
}

// ---------------------------------------------------------------------------
extern "C" void kernel_launch(void* const* d_in, const int* in_sizes, int n_in,
                              void* d_out, int out_size)
{
    const float* x    = (const float*)d_in[0];
    const int*   mask = (const int*)d_in[1];
    const float* Wq   = (const float*)d_in[2];
    const float* bq   = (const float*)d_in[3];
    const float* Wk   = (const float*)d_in[4];
    const float* bk   = (const float*)d_in[5];
    const float* Wv   = (const float*)d_in[6];
    const float* bv   = (const float*)d_in[7];
    const float* rel  = (const float*)d_in[8];
    const float* Wpk  = (const float*)d_in[9];
    const float* bpk  = (const float*)d_in[10];
    const float* Wpq  = (const float*)d_in[11];
    const float* bpq  = (const float*)d_in[12];
    const float* Wo   = (const float*)d_in[13];
    const float* bo   = (const float*)d_in[14];
    float* out = (float*)d_out;

    float* buf = nullptr;
    cudaGetSymbolAddress((void**)&buf, g_buf);
    float* q      = buf;
    float* k      = q + QSZ;
    float* v      = k + QSZ;
    float* pk     = v + QSZ;
    float* pq     = pk + PSZ;
    float* logits = pq + PSZ;
    float* vals   = logits + LSZ;

    cudaFuncSetAttribute((const void*)logits_kernel,
                         cudaFuncAttributeMaxDynamicSharedMemorySize, LOGITS_SMEM);

    // 1) Fused QKV projection: x(3072x512) -> q,k,v in [B,H,S,D]
    sgemm128<1><<<dim3(24, 12), 256>>>(x, Wq, Wk, Wv, bq, bk, bv, q, k, v, BB * SS, IND);

    // 2) Positional projections: only 767 distinct relative rows needed.
    //    rel index = (j-i)+511, j-i in [-383,383] -> rows 128..894.
    sgemm128<2><<<dim3(6, 4), 256>>>(rel + 128 * IND, Wpk, nullptr, nullptr,
                                     bpk, nullptr, nullptr, pk, nullptr, nullptr, RR, IND);
    sgemm128<2><<<dim3(6, 4), 256>>>(rel + 128 * IND, Wpq, nullptr, nullptr,
                                     bpq, nullptr, nullptr, pq, nullptr, nullptr, RR, IND);

    // 3) Fused disentangled logits (c2c + c2p + p2c, scaled, masked)
    logits_kernel<<<dim3(6, 6, 64), dim3(16, 16), LOGITS_SMEM>>>(q, k, pk, pq, logits, mask);

    // 4) Softmax
    softmax_kernel<<<BB * HH * SS, 128>>>(logits);

    // 5) attn @ V -> vals in [B,S,E]
    av_kernel<<<dim3(6, 64), dim3(16, 16)>>>(logits, v, vals);

    // 6) Output projection
    sgemm128<0><<<dim3(24, 4), 256>>>(vals, Wo, nullptr, nullptr,
                                      bo, nullptr, nullptr, out, nullptr, nullptr, BB * SS, EE);
}

// round 2
// speedup vs baseline: 1.7698x; 1.7698x over previous
#include <cuda_runtime.h>
#include <cstdint>

#define BB 8
#define SS 384
#define IND 512
#define EE 512
#define HH 8
#define DD 64
#define RR 767              // distinct (j-i) offsets
#define SCALEF 0.07216878364870323f   // 1/sqrt(64*3)

#define QSZ (BB*HH*SS*DD)
#define PSZ (HH*RR*DD)
#define LSZ (BB*HH*SS*SS)
#define VSZ (BB*SS*EE)

__device__ float g_buf[3*QSZ + 2*PSZ + LSZ + VSZ];

__device__ __forceinline__ uint32_t f2tf(float f) {
    uint32_t r;
    asm("cvt.rna.tf32.f32 %0, %1;" : "=r"(r) : "f"(f));
    return r;
}

__device__ __forceinline__ void mma_tf32(float c[4], uint32_t a0, uint32_t a1, uint32_t a2, uint32_t a3,
                                         uint32_t b0, uint32_t b1) {
    asm volatile("mma.sync.aligned.m16n8k8.row.col.f32.tf32.tf32.f32 "
                 "{%0,%1,%2,%3}, {%4,%5,%6,%7}, {%8,%9}, {%0,%1,%2,%3};"
                 : "+f"(c[0]), "+f"(c[1]), "+f"(c[2]), "+f"(c[3])
                 : "r"(a0), "r"(a1), "r"(a2), "r"(a3), "r"(b0), "r"(b1));
}

// ---------------------------------------------------------------------------
// Tensor-core GEMM: C[M,N] = A[M,K] @ W[N,K]^T + bias  (tf32 mma.sync)
// 128x128 block, 8 warps (2x4), each warp 64x32 = 4x4 m16n8k8 tiles.
// MODE 0: row-major C (stride 512). MODE 1: fused QKV (N=1536, scatter [B,H,S,D]).
// MODE 2: pos projection (M=767, scatter [H,RR,D]).
// ---------------------------------------------------------------------------
template<int MODE>
__launch_bounds__(256)
__global__ void mma_gemm(const float* __restrict__ A,
                         const float* __restrict__ W0, const float* __restrict__ W1, const float* __restrict__ W2,
                         const float* __restrict__ b0, const float* __restrict__ b1, const float* __restrict__ b2,
                         float* __restrict__ o0, float* __restrict__ o1, float* __restrict__ o2,
                         int M, int K)
{
    __shared__ uint32_t As[128][36];
    __shared__ uint32_t Ws[128][36];

    const int tid = threadIdx.x;
    const int m0 = blockIdx.x * 128;
    const int n0 = blockIdx.y * 128;

    const float* W = W0;
    const float* bias = b0;
    int which = 0;
    if (MODE == 1) {
        which = n0 >> 9;
        W    = (which == 0) ? W0 : (which == 1) ? W1 : W2;
        bias = (which == 0) ? b0 : (which == 1) ? b1 : b2;
    }
    const int nW0 = (MODE == 1) ? (n0 & 511) : n0;

    const int w = tid >> 5;
    const int lane = tid & 31;
    const int g = lane >> 2;     // group id
    const int t = lane & 3;      // thread in group
    const int mrow = (w >> 2) * 64;   // warp row base within block
    const int wcol = (w & 3) * 32;    // warp col base within block

    const int srow = tid >> 3;        // 0..31 (staging)
    const int skq  = (tid & 7) * 4;   // 0..28 step 4

    float acc[4][4][4];
#pragma unroll
    for (int mt = 0; mt < 4; mt++)
#pragma unroll
        for (int nt = 0; nt < 4; nt++)
#pragma unroll
            for (int i = 0; i < 4; i++) acc[mt][nt][i] = 0.f;

    for (int k0 = 0; k0 < K; k0 += 32) {
        if (k0) __syncthreads();
        // stage A (128x32) and W (128x32), converting to tf32
#pragma unroll
        for (int rr = 0; rr < 4; rr++) {
            const int row = rr * 32 + srow;
            float4 av = make_float4(0.f, 0.f, 0.f, 0.f);
            if (MODE != 2 || (m0 + row) < M)
                av = *(const float4*)(A + (size_t)(m0 + row) * K + k0 + skq);
            uint4 at;
            at.x = f2tf(av.x); at.y = f2tf(av.y); at.z = f2tf(av.z); at.w = f2tf(av.w);
            *(uint4*)&As[row][skq] = at;
            float4 wv = *(const float4*)(W + (size_t)(nW0 + row) * K + k0 + skq);
            uint4 wt;
            wt.x = f2tf(wv.x); wt.y = f2tf(wv.y); wt.z = f2tf(wv.z); wt.w = f2tf(wv.w);
            *(uint4*)&Ws[row][skq] = wt;
        }
        __syncthreads();

#pragma unroll
        for (int ks = 0; ks < 4; ks++) {
            const int kk = ks * 8;
            uint32_t a[4][4], bfr[4][2];
#pragma unroll
            for (int mt = 0; mt < 4; mt++) {
                const int r = mrow + mt * 16 + g;
                a[mt][0] = As[r][kk + t];
                a[mt][1] = As[r + 8][kk + t];
                a[mt][2] = As[r][kk + t + 4];
                a[mt][3] = As[r + 8][kk + t + 4];
            }
#pragma unroll
            for (int nt = 0; nt < 4; nt++) {
                const int r = wcol + nt * 8 + g;
                bfr[nt][0] = Ws[r][kk + t];
                bfr[nt][1] = Ws[r][kk + t + 4];
            }
#pragma unroll
            for (int mt = 0; mt < 4; mt++)
#pragma unroll
                for (int nt = 0; nt < 4; nt++)
                    mma_tf32(acc[mt][nt], a[mt][0], a[mt][1], a[mt][2], a[mt][3],
                             bfr[nt][0], bfr[nt][1]);
        }
    }

    // epilogue
#pragma unroll
    for (int mt = 0; mt < 4; mt++) {
        const int rm0 = m0 + mrow + mt * 16 + g;
        const int rm1 = rm0 + 8;
#pragma unroll
        for (int nt = 0; nt < 4; nt++) {
            const int cn = wcol + nt * 8 + t * 2;   // local col
            const int n = n0 + cn;
            const float* cc = acc[mt][nt];
            if (MODE == 0) {
                const float bz0 = bias[n], bz1 = bias[n + 1];
                float2 v0 = make_float2(cc[0] + bz0, cc[1] + bz1);
                float2 v1 = make_float2(cc[2] + bz0, cc[3] + bz1);
                *(float2*)&o0[(size_t)rm0 * 512 + n] = v0;
                *(float2*)&o0[(size_t)rm1 * 512 + n] = v1;
            } else if (MODE == 1) {
                const int nn = n & 511;
                const float bz0 = bias[nn], bz1 = bias[nn + 1];
                float* o = (which == 0) ? o0 : (which == 1) ? o1 : o2;
                const int h = nn >> 6, d = nn & 63;
                {
                    const int b = rm0 / SS, s = rm0 % SS;
                    float* p = o + (((size_t)(b * HH + h)) * SS + s) * DD + d;
                    p[0] = cc[0] + bz0; p[1] = cc[1] + bz1;
                }
                {
                    const int b = rm1 / SS, s = rm1 % SS;
                    float* p = o + (((size_t)(b * HH + h)) * SS + s) * DD + d;
                    p[0] = cc[2] + bz0; p[1] = cc[3] + bz1;
                }
            } else {
                const float bz0 = bias[n], bz1 = bias[n + 1];
                const int h = n >> 6, d = n & 63;
                if (rm0 < M) {
                    float* p = o0 + ((size_t)h * RR + rm0) * DD + d;
                    p[0] = cc[0] + bz0; p[1] = cc[1] + bz1;
                }
                if (rm1 < M) {
                    float* p = o0 + ((size_t)h * RR + rm1) * DD + d;
                    p[0] = cc[2] + bz0; p[1] = cc[3] + bz1;
                }
            }
        }
    }
}

// ---------------------------------------------------------------------------
// Fused disentangled logits (unchanged from R1)
// ---------------------------------------------------------------------------
#define LOGITS_SMEM ((2*64*65 + 2*128*65) * (int)sizeof(float))

__launch_bounds__(256)
__global__ void logits_kernel(const float* __restrict__ gq, const float* __restrict__ gk,
                              const float* __restrict__ gpk, const float* __restrict__ gpq,
                              float* __restrict__ glog, const int* __restrict__ mask)
{
    extern __shared__ float sm[];
    float* Qs  = sm;
    float* Ks  = Qs + 64 * 65;
    float* PKs = Ks + 64 * 65;
    float* PQs = PKs + 128 * 65;

    const int bh = blockIdx.z;
    const int b = bh >> 3, h = bh & 7;
    const int i0 = blockIdx.x * 64;
    const int j0 = blockIdx.y * 64;
    const int tid = threadIdx.y * 16 + threadIdx.x;

    const float* qbase = gq + ((size_t)bh * SS + i0) * DD;
    const float* kbase = gk + ((size_t)bh * SS + j0) * DD;
    for (int tt = tid; tt < 64 * 16; tt += 256) {
        const int r = tt >> 4, c = (tt & 15) * 4;
        float4 v = *(const float4*)(qbase + r * DD + c);
        Qs[r * 65 + c] = v.x; Qs[r * 65 + c + 1] = v.y; Qs[r * 65 + c + 2] = v.z; Qs[r * 65 + c + 3] = v.w;
        float4 w = *(const float4*)(kbase + r * DD + c);
        Ks[r * 65 + c] = w.x; Ks[r * 65 + c + 1] = w.y; Ks[r * 65 + c + 2] = w.z; Ks[r * 65 + c + 3] = w.w;
    }
    const int base_r = j0 - i0 + 320;
    const float* pkb = gpk + (size_t)h * RR * DD;
    const float* pqb = gpq + (size_t)h * RR * DD;
    for (int tt = tid; tt < 128 * 16; tt += 256) {
        const int r = tt >> 4, c = (tt & 15) * 4;
        float4 v = make_float4(0.f, 0.f, 0.f, 0.f);
        float4 w = make_float4(0.f, 0.f, 0.f, 0.f);
        if (r < 127) {
            const int rg = base_r + r;
            v = *(const float4*)(pkb + (size_t)rg * DD + c);
            w = *(const float4*)(pqb + (size_t)rg * DD + c);
        }
        PKs[r * 65 + c] = v.x; PKs[r * 65 + c + 1] = v.y; PKs[r * 65 + c + 2] = v.z; PKs[r * 65 + c + 3] = v.w;
        PQs[r * 65 + c] = w.x; PQs[r * 65 + c + 1] = w.y; PQs[r * 65 + c + 2] = w.z; PQs[r * 65 + c + 3] = w.w;
    }
    __syncthreads();

    const int il = threadIdx.y * 4, jl = threadIdx.x * 4;
    const int rb = jl - il + 60;
    float acc[4][4];
#pragma unroll
    for (int a = 0; a < 4; a++)
#pragma unroll
        for (int c = 0; c < 4; c++) acc[a][c] = 0.f;

#pragma unroll 4
    for (int d = 0; d < 64; d++) {
        float qv[4], kv[4], pk7[7], pq7[7];
#pragma unroll
        for (int a = 0; a < 4; a++) qv[a] = Qs[(il + a) * 65 + d];
#pragma unroll
        for (int c = 0; c < 4; c++) kv[c] = Ks[(jl + c) * 65 + d];
#pragma unroll
        for (int tt = 0; tt < 7; tt++) {
            pk7[tt] = PKs[(rb + tt) * 65 + d];
            pq7[tt] = PQs[(rb + tt) * 65 + d];
        }
#pragma unroll
        for (int a = 0; a < 4; a++)
#pragma unroll
            for (int c = 0; c < 4; c++) {
                const int tt = c - a + 3;
                acc[a][c] = fmaf(qv[a], kv[c] + pk7[tt], fmaf(pq7[tt], kv[c], acc[a][c]));
            }
    }

    float* lb = glog + ((size_t)bh * SS + i0) * SS;
#pragma unroll
    for (int a = 0; a < 4; a++) {
        const int i = il + a;
#pragma unroll
        for (int c = 0; c < 4; c++) {
            const int j = j0 + jl + c;
            float l = acc[a][c] * SCALEF;
            if (mask[b * SS + j] == 0) l = -9.0e15f;
            lb[(size_t)i * SS + j] = l;
        }
    }
}

// ---------------------------------------------------------------------------
__launch_bounds__(128)
__global__ void softmax_kernel(float* __restrict__ glog)
{
    float* p = glog + (size_t)blockIdx.x * SS;
    const int t = threadIdx.x;
    float v0 = p[t], v1 = p[t + 128], v2 = p[t + 256];

    __shared__ float red[4];
    float m = fmaxf(v0, fmaxf(v1, v2));
#pragma unroll
    for (int o = 16; o > 0; o >>= 1) m = fmaxf(m, __shfl_xor_sync(0xffffffffu, m, o));
    if ((t & 31) == 0) red[t >> 5] = m;
    __syncthreads();
    m = fmaxf(fmaxf(red[0], red[1]), fmaxf(red[2], red[3]));

    v0 = __expf(v0 - m); v1 = __expf(v1 - m); v2 = __expf(v2 - m);
    float s = v0 + v1 + v2;
#pragma unroll
    for (int o = 16; o > 0; o >>= 1) s += __shfl_xor_sync(0xffffffffu, s, o);
    __syncthreads();
    if ((t & 31) == 0) red[t >> 5] = s;
    __syncthreads();
    s = red[0] + red[1] + red[2] + red[3];

    const float inv = 1.0f / s;
    p[t] = v0 * inv; p[t + 128] = v1 * inv; p[t + 256] = v2 * inv;
}

// ---------------------------------------------------------------------------
__launch_bounds__(256)
__global__ void av_kernel(const float* __restrict__ attn_all, const float* __restrict__ gv,
                          float* __restrict__ vals)
{
    __shared__ float As[64][33];
    __shared__ float Vs[32][65];
    const int bh = blockIdx.y;
    const int b = bh >> 3, h = bh & 7;
    const int i0 = blockIdx.x * 64;
    const int tid = threadIdx.y * 16 + threadIdx.x;

    const float* attn = attn_all + ((size_t)bh * SS + i0) * SS;
    const float* vb = gv + (size_t)bh * SS * DD;

    float acc[4][4];
#pragma unroll
    for (int a = 0; a < 4; a++)
#pragma unroll
        for (int c = 0; c < 4; c++) acc[a][c] = 0.f;

    for (int k0 = 0; k0 < SS; k0 += 32) {
        for (int tt = tid; tt < 64 * 8; tt += 256) {
            const int r = tt >> 3, c = (tt & 7) * 4;
            float4 v = *(const float4*)(attn + (size_t)r * SS + k0 + c);
            As[r][c] = v.x; As[r][c + 1] = v.y; As[r][c + 2] = v.z; As[r][c + 3] = v.w;
        }
        for (int tt = tid; tt < 32 * 16; tt += 256) {
            const int r = tt >> 4, c = (tt & 15) * 4;
            float4 v = *(const float4*)(vb + (size_t)(k0 + r) * DD + c);
            Vs[r][c] = v.x; Vs[r][c + 1] = v.y; Vs[r][c + 2] = v.z; Vs[r][c + 3] = v.w;
        }
        __syncthreads();
#pragma unroll 8
        for (int kk = 0; kk < 32; kk++) {
            float a4[4], v4[4];
#pragma unroll
            for (int a = 0; a < 4; a++) a4[a] = As[threadIdx.y * 4 + a][kk];
#pragma unroll
            for (int c = 0; c < 4; c++) v4[c] = Vs[kk][threadIdx.x * 4 + c];
#pragma unroll
            for (int a = 0; a < 4; a++)
#pragma unroll
                for (int c = 0; c < 4; c++) acc[a][c] = fmaf(a4[a], v4[c], acc[a][c]);
        }
        __syncthreads();
    }

#pragma unroll
    for (int a = 0; a < 4; a++) {
        const int i = i0 + threadIdx.y * 4 + a;
#pragma unroll
        for (int c = 0; c < 4; c++) {
            const int d = threadIdx.x * 4 + c;
            vals[((size_t)b * SS + i) * EE + h * DD + d] = acc[a][c];
        }
    }
}

// ---------------------------------------------------------------------------
extern "C" void kernel_launch(void* const* d_in, const int* in_sizes, int n_in,
                              void* d_out, int out_size)
{
    const float* x    = (const float*)d_in[0];
    const int*   mask = (const int*)d_in[1];
    const float* Wq   = (const float*)d_in[2];
    const float* bq   = (const float*)d_in[3];
    const float* Wk   = (const float*)d_in[4];
    const float* bk   = (const float*)d_in[5];
    const float* Wv   = (const float*)d_in[6];
    const float* bv   = (const float*)d_in[7];
    const float* rel  = (const float*)d_in[8];
    const float* Wpk  = (const float*)d_in[9];
    const float* bpk  = (const float*)d_in[10];
    const float* Wpq  = (const float*)d_in[11];
    const float* bpq  = (const float*)d_in[12];
    const float* Wo   = (const float*)d_in[13];
    const float* bo   = (const float*)d_in[14];
    float* out = (float*)d_out;

    float* buf = nullptr;
    cudaGetSymbolAddress((void**)&buf, g_buf);
    float* q      = buf;
    float* k      = q + QSZ;
    float* v      = k + QSZ;
    float* pk     = v + QSZ;
    float* pq     = pk + PSZ;
    float* logits = pq + PSZ;
    float* vals   = logits + LSZ;

    cudaFuncSetAttribute((const void*)logits_kernel,
                         cudaFuncAttributeMaxDynamicSharedMemorySize, LOGITS_SMEM);

    // 1) Fused QKV projection (tf32 mma): x(3072x512) -> q,k,v in [B,H,S,D]
    mma_gemm<1><<<dim3(24, 12), 256>>>(x, Wq, Wk, Wv, bq, bk, bv, q, k, v, BB * SS, IND);

    // 2) Positional projections (767 distinct relative rows; rel rows 128..894)
    mma_gemm<2><<<dim3(6, 4), 256>>>(rel + 128 * IND, Wpk, nullptr, nullptr,
                                     bpk, nullptr, nullptr, pk, nullptr, nullptr, RR, IND);
    mma_gemm<2><<<dim3(6, 4), 256>>>(rel + 128 * IND, Wpq, nullptr, nullptr,
                                     bpq, nullptr, nullptr, pq, nullptr, nullptr, RR, IND);

    // 3) Fused disentangled logits (c2c + c2p + p2c, scaled, masked)
    logits_kernel<<<dim3(6, 6, 64), dim3(16, 16), LOGITS_SMEM>>>(q, k, pk, pq, logits, mask);

    // 4) Softmax
    softmax_kernel<<<BB * HH * SS, 128>>>(logits);

    // 5) attn @ V
    av_kernel<<<dim3(6, 64), dim3(16, 16)>>>(logits, v, vals);

    // 6) Output projection
    mma_gemm<0><<<dim3(24, 4), 256>>>(vals, Wo, nullptr, nullptr,
                                      bo, nullptr, nullptr, out, nullptr, nullptr, BB * SS, EE);
}

// round 3
// speedup vs baseline: 2.6167x; 1.4785x over previous
#include <cuda_runtime.h>
#include <cstdint>

#define BB 8
#define SS 384
#define IND 512
#define EE 512
#define HH 8
#define DD 64
#define RR 767
#define SCALEF 0.07216878364870323f   // 1/sqrt(64*3)

#define QSZ (BB*HH*SS*DD)
#define PSZ (HH*RR*DD)
#define VSZ (BB*SS*EE)

__device__ float g_buf[3*QSZ + 2*PSZ + VSZ];

__device__ __forceinline__ uint32_t f2tf(float f) {
    uint32_t r;
    asm("cvt.rna.tf32.f32 %0, %1;" : "=r"(r) : "f"(f));
    return r;
}

__device__ __forceinline__ void mma_tf32(float c[4], uint32_t a0, uint32_t a1, uint32_t a2, uint32_t a3,
                                         uint32_t b0, uint32_t b1) {
    asm volatile("mma.sync.aligned.m16n8k8.row.col.f32.tf32.tf32.f32 "
                 "{%0,%1,%2,%3}, {%4,%5,%6,%7}, {%8,%9}, {%0,%1,%2,%3};"
                 : "+f"(c[0]), "+f"(c[1]), "+f"(c[2]), "+f"(c[3])
                 : "r"(a0), "r"(a1), "r"(a2), "r"(a3), "r"(b0), "r"(b1));
}

// ---------------------------------------------------------------------------
// Tensor-core GEMM: C[M,N] = A[M,K] @ W[N,K]^T + bias  (tf32 mma.sync)
// MODE 0: row-major C. MODE 1: fused QKV scatter [B,H,S,D]. MODE 2: pos [H,RR,D].
// ---------------------------------------------------------------------------
template<int MODE>
__launch_bounds__(256)
__global__ void mma_gemm(const float* __restrict__ A,
                         const float* __restrict__ W0, const float* __restrict__ W1, const float* __restrict__ W2,
                         const float* __restrict__ b0, const float* __restrict__ b1, const float* __restrict__ b2,
                         float* __restrict__ o0, float* __restrict__ o1, float* __restrict__ o2,
                         int M, int K)
{
    __shared__ uint32_t As[128][36];
    __shared__ uint32_t Ws[128][36];

    const int tid = threadIdx.x;
    const int m0 = blockIdx.x * 128;
    const int n0 = blockIdx.y * 128;

    const float* W = W0;
    const float* bias = b0;
    int which = 0;
    if (MODE == 1) {
        which = n0 >> 9;
        W    = (which == 0) ? W0 : (which == 1) ? W1 : W2;
        bias = (which == 0) ? b0 : (which == 1) ? b1 : b2;
    }
    const int nW0 = (MODE == 1) ? (n0 & 511) : n0;

    const int w = tid >> 5;
    const int lane = tid & 31;
    const int g = lane >> 2;
    const int t = lane & 3;
    const int mrow = (w >> 2) * 64;
    const int wcol = (w & 3) * 32;

    const int srow = tid >> 3;
    const int skq  = (tid & 7) * 4;

    float acc[4][4][4];
#pragma unroll
    for (int mt = 0; mt < 4; mt++)
#pragma unroll
        for (int nt = 0; nt < 4; nt++)
#pragma unroll
            for (int i = 0; i < 4; i++) acc[mt][nt][i] = 0.f;

    for (int k0 = 0; k0 < K; k0 += 32) {
        if (k0) __syncthreads();
#pragma unroll
        for (int rr = 0; rr < 4; rr++) {
            const int row = rr * 32 + srow;
            float4 av = make_float4(0.f, 0.f, 0.f, 0.f);
            if (MODE != 2 || (m0 + row) < M)
                av = *(const float4*)(A + (size_t)(m0 + row) * K + k0 + skq);
            uint4 at;
            at.x = f2tf(av.x); at.y = f2tf(av.y); at.z = f2tf(av.z); at.w = f2tf(av.w);
            *(uint4*)&As[row][skq] = at;
            float4 wv = *(const float4*)(W + (size_t)(nW0 + row) * K + k0 + skq);
            uint4 wt;
            wt.x = f2tf(wv.x); wt.y = f2tf(wv.y); wt.z = f2tf(wv.z); wt.w = f2tf(wv.w);
            *(uint4*)&Ws[row][skq] = wt;
        }
        __syncthreads();

#pragma unroll
        for (int ks = 0; ks < 4; ks++) {
            const int kk = ks * 8;
            uint32_t a[4][4], bfr[4][2];
#pragma unroll
            for (int mt = 0; mt < 4; mt++) {
                const int r = mrow + mt * 16 + g;
                a[mt][0] = As[r][kk + t];
                a[mt][1] = As[r + 8][kk + t];
                a[mt][2] = As[r][kk + t + 4];
                a[mt][3] = As[r + 8][kk + t + 4];
            }
#pragma unroll
            for (int nt = 0; nt < 4; nt++) {
                const int r = wcol + nt * 8 + g;
                bfr[nt][0] = Ws[r][kk + t];
                bfr[nt][1] = Ws[r][kk + t + 4];
            }
#pragma unroll
            for (int mt = 0; mt < 4; mt++)
#pragma unroll
                for (int nt = 0; nt < 4; nt++)
                    mma_tf32(acc[mt][nt], a[mt][0], a[mt][1], a[mt][2], a[mt][3],
                             bfr[nt][0], bfr[nt][1]);
        }
    }

#pragma unroll
    for (int mt = 0; mt < 4; mt++) {
        const int rm0 = m0 + mrow + mt * 16 + g;
        const int rm1 = rm0 + 8;
#pragma unroll
        for (int nt = 0; nt < 4; nt++) {
            const int cn = wcol + nt * 8 + t * 2;
            const int n = n0 + cn;
            const float* cc = acc[mt][nt];
            if (MODE == 0) {
                const float bz0 = bias[n], bz1 = bias[n + 1];
                *(float2*)&o0[(size_t)rm0 * 512 + n] = make_float2(cc[0] + bz0, cc[1] + bz1);
                *(float2*)&o0[(size_t)rm1 * 512 + n] = make_float2(cc[2] + bz0, cc[3] + bz1);
            } else if (MODE == 1) {
                const int nn = n & 511;
                const float bz0 = bias[nn], bz1 = bias[nn + 1];
                float* o = (which == 0) ? o0 : (which == 1) ? o1 : o2;
                const int h = nn >> 6, d = nn & 63;
                {
                    const int b = rm0 / SS, s = rm0 % SS;
                    float* p = o + (((size_t)(b * HH + h)) * SS + s) * DD + d;
                    p[0] = cc[0] + bz0; p[1] = cc[1] + bz1;
                }
                {
                    const int b = rm1 / SS, s = rm1 % SS;
                    float* p = o + (((size_t)(b * HH + h)) * SS + s) * DD + d;
                    p[0] = cc[2] + bz0; p[1] = cc[3] + bz1;
                }
            } else {
                const float bz0 = bias[n], bz1 = bias[n + 1];
                const int h = n >> 6, d = n & 63;
                if (rm0 < M) {
                    float* p = o0 + ((size_t)h * RR + rm0) * DD + d;
                    p[0] = cc[0] + bz0; p[1] = cc[1] + bz1;
                }
                if (rm1 < M) {
                    float* p = o0 + ((size_t)h * RR + rm1) * DD + d;
                    p[0] = cc[2] + bz0; p[1] = cc[3] + bz1;
                }
            }
        }
    }
}

// ---------------------------------------------------------------------------
// Fused flash attention with disentangled relative-position terms.
// One block per (bh, 64-row i-tile). Loops over 64-col j-tiles:
//   S = (Q@K^T + gather(Q@PKband^T) + gather(PQband@K^T)) * SCALE  (tf32 MMA)
//   online softmax, O += P@V (tf32 MMA), final O/l -> vals [B,S,E].
// ---------------------------------------------------------------------------
#define T64P 68               // padded row length for 64-wide tiles
#define QPK_P 132             // padded row length for QPKs gather buffer
// smem (uint32 units): Qs,Ks,Vt,Ps: 64*68 each; PKb,PQb: 128*68 each; arrays 320
#define FL_U32 (4*64*T64P + 2*128*T64P + 320)
#define FL_SMEM (FL_U32 * 4)

__launch_bounds__(256, 1)
__global__ void flash_kernel(const float* __restrict__ gq, const float* __restrict__ gk,
                             const float* __restrict__ gv,
                             const float* __restrict__ gpk, const float* __restrict__ gpq,
                             const int* __restrict__ mask, float* __restrict__ vals)
{
    extern __shared__ uint32_t sm[];
    uint32_t* Qs = sm;
    uint32_t* Ks = sm + 64 * T64P;
    uint32_t* Vt = sm + 2 * 64 * T64P;
    uint32_t* Ps = sm + 3 * 64 * T64P;
    uint32_t* PKb = sm + 4 * 64 * T64P;        // [128][68] band; reused as QPKs [64][132] f32
    uint32_t* PQb = PKb + 128 * T64P;          // [128][68] band; reused as PQKs [128][68] f32
    float* QPKs = (float*)PKb;
    float* PQKs = (float*)PQb;
    float* maskb = (float*)(PQb + 128 * T64P); // [64] 1/0
    float* pm    = maskb + 64;                 // [2][64]
    float* psum  = pm + 128;                   // [2][64]

    const int bh = blockIdx.y;
    const int b = bh >> 3, h = bh & 7;
    const int i0 = blockIdx.x * 64;
    const int tid = threadIdx.x;
    const int w = tid >> 5, lane = tid & 31;
    const int g = lane >> 2, t = lane & 3;
    const int wm = w & 3, wn = w >> 2;
    const int r0 = wm * 16 + g;                // this thread's S/O row slot 0 (slot 1 = r0+8)

    // Load Q tile (64x64) -> tf32 smem
    {
        const float* qb = gq + ((size_t)bh * SS + i0) * DD;
        const int r = tid >> 2, c = (tid & 3) * 16;
#pragma unroll
        for (int u = 0; u < 4; u++) {
            float4 v = *(const float4*)(qb + r * DD + c + u * 4);
            uint32_t* dst = &Qs[r * T64P + c + u * 4];
            dst[0] = f2tf(v.x); dst[1] = f2tf(v.y); dst[2] = f2tf(v.z); dst[3] = f2tf(v.w);
        }
    }

    float oacc[4][4];
#pragma unroll
    for (int nt = 0; nt < 4; nt++)
#pragma unroll
        for (int i = 0; i < 4; i++) oacc[nt][i] = 0.f;
    float mrun[2] = {-INFINITY, -INFINITY};
    float lrun[2] = {0.f, 0.f};

    for (int j0 = 0; j0 < SS; j0 += 64) {
        // ---- stage K, V^T, bands, mask ----
        {
            const float* kb = gk + ((size_t)bh * SS + j0) * DD;
            const float* vb = gv + ((size_t)bh * SS + j0) * DD;
            const int r = tid >> 2, c = (tid & 3) * 16;
#pragma unroll
            for (int u = 0; u < 4; u++) {
                float4 kv = *(const float4*)(kb + r * DD + c + u * 4);
                uint32_t* dk = &Ks[r * T64P + c + u * 4];
                dk[0] = f2tf(kv.x); dk[1] = f2tf(kv.y); dk[2] = f2tf(kv.z); dk[3] = f2tf(kv.w);
                float4 vv = *(const float4*)(vb + r * DD + c + u * 4);
                Vt[(c + u * 4 + 0) * T64P + r] = f2tf(vv.x);
                Vt[(c + u * 4 + 1) * T64P + r] = f2tf(vv.y);
                Vt[(c + u * 4 + 2) * T64P + r] = f2tf(vv.z);
                Vt[(c + u * 4 + 3) * T64P + r] = f2tf(vv.w);
            }
        }
        {
            const int base_r = j0 - i0 + 320;   // global rel row of band row 0
            const float* pkp = gpk + ((size_t)h * RR + base_r) * DD;
            const float* pqp = gpq + ((size_t)h * RR + base_r) * DD;
            for (int tt = tid; tt < 128 * 16; tt += 256) {
                const int r = tt >> 4, c = (tt & 15) * 4;
                float4 v = make_float4(0.f, 0.f, 0.f, 0.f);
                float4 u2 = make_float4(0.f, 0.f, 0.f, 0.f);
                if (r < 127) {
                    v = *(const float4*)(pkp + (size_t)r * DD + c);
                    u2 = *(const float4*)(pqp + (size_t)r * DD + c);
                }
                uint32_t* dp = &PKb[r * T64P + c];
                dp[0] = f2tf(v.x); dp[1] = f2tf(v.y); dp[2] = f2tf(v.z); dp[3] = f2tf(v.w);
                uint32_t* dq = &PQb[r * T64P + c];
                dq[0] = f2tf(u2.x); dq[1] = f2tf(u2.y); dq[2] = f2tf(u2.z); dq[3] = f2tf(u2.w);
            }
        }
        if (tid < 64) maskb[tid] = (mask[b * SS + j0 + tid] == 0) ? 0.f : 1.f;
        __syncthreads();

        // ---- MMAs: S_qk (16x32/warp), QPK (16x64/warp), PQK (16x64/warp) ----
        float sacc[4][4];
        float qpk[8][4];
        float pqk[8][4];
#pragma unroll
        for (int nt = 0; nt < 4; nt++)
#pragma unroll
            for (int i = 0; i < 4; i++) sacc[nt][i] = 0.f;
#pragma unroll
        for (int nt = 0; nt < 8; nt++)
#pragma unroll
            for (int i = 0; i < 4; i++) { qpk[nt][i] = 0.f; pqk[nt][i] = 0.f; }

#pragma unroll
        for (int ks = 0; ks < 8; ks++) {
            const int kk = ks * 8;
            uint32_t aq[4], apq[4], bk[8][2], bpk[8][2];
            aq[0] = Qs[r0 * T64P + kk + t];
            aq[1] = Qs[(r0 + 8) * T64P + kk + t];
            aq[2] = Qs[r0 * T64P + kk + t + 4];
            aq[3] = Qs[(r0 + 8) * T64P + kk + t + 4];
            const int rp = w * 16 + g;
            apq[0] = PQb[rp * T64P + kk + t];
            apq[1] = PQb[(rp + 8) * T64P + kk + t];
            apq[2] = PQb[rp * T64P + kk + t + 4];
            apq[3] = PQb[(rp + 8) * T64P + kk + t + 4];
#pragma unroll
            for (int nt = 0; nt < 8; nt++) {
                const int rk = nt * 8 + g;
                bk[nt][0] = Ks[rk * T64P + kk + t];
                bk[nt][1] = Ks[rk * T64P + kk + t + 4];
                const int rb2 = wn * 64 + nt * 8 + g;
                bpk[nt][0] = PKb[rb2 * T64P + kk + t];
                bpk[nt][1] = PKb[rb2 * T64P + kk + t + 4];
            }
#pragma unroll
            for (int nt = 0; nt < 4; nt++)
                mma_tf32(sacc[nt], aq[0], aq[1], aq[2], aq[3],
                         bk[wn * 4 + nt][0], bk[wn * 4 + nt][1]);
#pragma unroll
            for (int nt = 0; nt < 8; nt++)
                mma_tf32(qpk[nt], aq[0], aq[1], aq[2], aq[3], bpk[nt][0], bpk[nt][1]);
#pragma unroll
            for (int nt = 0; nt < 8; nt++)
                mma_tf32(pqk[nt], apq[0], apq[1], apq[2], apq[3], bk[nt][0], bk[nt][1]);
        }
        __syncthreads();   // bands fully consumed; safe to overwrite with gather results

        // ---- spill QPK/PQK to smem (aliased over band buffers) ----
        {
#pragma unroll
            for (int nt = 0; nt < 8; nt++) {
                const int cq = wn * 64 + nt * 8 + t * 2;
                QPKs[r0 * QPK_P + cq]       = qpk[nt][0];
                QPKs[r0 * QPK_P + cq + 1]   = qpk[nt][1];
                QPKs[(r0 + 8) * QPK_P + cq]     = qpk[nt][2];
                QPKs[(r0 + 8) * QPK_P + cq + 1] = qpk[nt][3];
            }
            const int rr = w * 16 + g;
#pragma unroll
            for (int nt = 0; nt < 8; nt++) {
                const int cl = nt * 8 + t * 2;
                PQKs[rr * T64P + cl]       = pqk[nt][0];
                PQKs[rr * T64P + cl + 1]   = pqk[nt][1];
                PQKs[(rr + 8) * T64P + cl]     = pqk[nt][2];
                PQKs[(rr + 8) * T64P + cl + 1] = pqk[nt][3];
            }
        }
        __syncthreads();

        // ---- combine + mask + scale; tile row max ----
        float pvals[2][8];
        float tmax[2] = {-INFINITY, -INFINITY};
#pragma unroll
        for (int nt = 0; nt < 4; nt++) {
            const int ljb = wn * 32 + nt * 8 + t * 2;
#pragma unroll
            for (int e = 0; e < 2; e++) {
                const int lj = ljb + e;
                const float mk = maskb[lj];
                const int t0 = lj - r0 + 63;
                float s0 = (sacc[nt][e] + QPKs[r0 * QPK_P + t0] + PQKs[t0 * T64P + lj]) * SCALEF;
                s0 = (mk != 0.f) ? s0 : -9.0e15f;
                const int t1 = t0 - 8;
                float s1 = (sacc[nt][2 + e] + QPKs[(r0 + 8) * QPK_P + t1] + PQKs[t1 * T64P + lj]) * SCALEF;
                s1 = (mk != 0.f) ? s1 : -9.0e15f;
                pvals[0][nt * 2 + e] = s0;
                pvals[1][nt * 2 + e] = s1;
                tmax[0] = fmaxf(tmax[0], s0);
                tmax[1] = fmaxf(tmax[1], s1);
            }
        }
#pragma unroll
        for (int r = 0; r < 2; r++) {
            tmax[r] = fmaxf(tmax[r], __shfl_xor_sync(0xffffffffu, tmax[r], 1));
            tmax[r] = fmaxf(tmax[r], __shfl_xor_sync(0xffffffffu, tmax[r], 2));
        }
        if (t == 0) { pm[wn * 64 + r0] = tmax[0]; pm[wn * 64 + r0 + 8] = tmax[1]; }
        __syncthreads();

        float mnew[2], alpha[2];
#pragma unroll
        for (int r = 0; r < 2; r++) {
            const int row = r0 + r * 8;
            const float mt2 = fmaxf(pm[row], pm[64 + row]);
            mnew[r] = fmaxf(mrun[r], mt2);
            alpha[r] = __expf(mrun[r] - mnew[r]);
            mrun[r] = mnew[r];
        }

        // ---- exp + row sums + write P (tf32) ----
        float tsum[2] = {0.f, 0.f};
#pragma unroll
        for (int q2 = 0; q2 < 8; q2++) {
            float p0 = __expf(pvals[0][q2] - mnew[0]);
            float p1 = __expf(pvals[1][q2] - mnew[1]);
            pvals[0][q2] = p0; pvals[1][q2] = p1;
            tsum[0] += p0; tsum[1] += p1;
        }
#pragma unroll
        for (int r = 0; r < 2; r++) {
            tsum[r] += __shfl_xor_sync(0xffffffffu, tsum[r], 1);
            tsum[r] += __shfl_xor_sync(0xffffffffu, tsum[r], 2);
        }
        if (t == 0) { psum[wn * 64 + r0] = tsum[0]; psum[wn * 64 + r0 + 8] = tsum[1]; }
#pragma unroll
        for (int nt = 0; nt < 4; nt++) {
            const int cb = wn * 32 + nt * 8 + t * 2;
            Ps[r0 * T64P + cb]       = f2tf(pvals[0][nt * 2]);
            Ps[r0 * T64P + cb + 1]   = f2tf(pvals[0][nt * 2 + 1]);
            Ps[(r0 + 8) * T64P + cb]     = f2tf(pvals[1][nt * 2]);
            Ps[(r0 + 8) * T64P + cb + 1] = f2tf(pvals[1][nt * 2 + 1]);
        }
        __syncthreads();

#pragma unroll
        for (int r = 0; r < 2; r++) {
            const int row = r0 + r * 8;
            lrun[r] = lrun[r] * alpha[r] + psum[row] + psum[64 + row];
        }
        // rescale O
#pragma unroll
        for (int nt = 0; nt < 4; nt++) {
            oacc[nt][0] *= alpha[0]; oacc[nt][1] *= alpha[0];
            oacc[nt][2] *= alpha[1]; oacc[nt][3] *= alpha[1];
        }

        // ---- O += P @ V ----
#pragma unroll
        for (int ks = 0; ks < 8; ks++) {
            const int kk = ks * 8;
            uint32_t ap[4], bv2[4][2];
            ap[0] = Ps[r0 * T64P + kk + t];
            ap[1] = Ps[(r0 + 8) * T64P + kk + t];
            ap[2] = Ps[r0 * T64P + kk + t + 4];
            ap[3] = Ps[(r0 + 8) * T64P + kk + t + 4];
#pragma unroll
            for (int nt = 0; nt < 4; nt++) {
                const int rv = wn * 32 + nt * 8 + g;
                bv2[nt][0] = Vt[rv * T64P + kk + t];
                bv2[nt][1] = Vt[rv * T64P + kk + t + 4];
            }
#pragma unroll
            for (int nt = 0; nt < 4; nt++)
                mma_tf32(oacc[nt], ap[0], ap[1], ap[2], ap[3], bv2[nt][0], bv2[nt][1]);
        }
        __syncthreads();   // before next iteration overwrites K/V/bands/Ps
    }

    // ---- finalize: O / l -> vals [B,S,E] ----
    const float inv0 = 1.f / lrun[0];
    const float inv1 = 1.f / lrun[1];
    const int row0 = i0 + r0;
#pragma unroll
    for (int nt = 0; nt < 4; nt++) {
        const int d = wn * 32 + nt * 8 + t * 2;
        float* p0 = &vals[((size_t)(b * SS + row0)) * EE + h * 64 + d];
        *(float2*)p0 = make_float2(oacc[nt][0] * inv0, oacc[nt][1] * inv0);
        float* p1 = &vals[((size_t)(b * SS + row0 + 8)) * EE + h * 64 + d];
        *(float2*)p1 = make_float2(oacc[nt][2] * inv1, oacc[nt][3] * inv1);
    }
}

// ---------------------------------------------------------------------------
extern "C" void kernel_launch(void* const* d_in, const int* in_sizes, int n_in,
                              void* d_out, int out_size)
{
    const float* x    = (const float*)d_in[0];
    const int*   mask = (const int*)d_in[1];
    const float* Wq   = (const float*)d_in[2];
    const float* bq   = (const float*)d_in[3];
    const float* Wk   = (const float*)d_in[4];
    const float* bk   = (const float*)d_in[5];
    const float* Wv   = (const float*)d_in[6];
    const float* bv   = (const float*)d_in[7];
    const float* rel  = (const float*)d_in[8];
    const float* Wpk  = (const float*)d_in[9];
    const float* bpk  = (const float*)d_in[10];
    const float* Wpq  = (const float*)d_in[11];
    const float* bpq  = (const float*)d_in[12];
    const float* Wo   = (const float*)d_in[13];
    const float* bo   = (const float*)d_in[14];
    float* out = (float*)d_out;

    float* buf = nullptr;
    cudaGetSymbolAddress((void**)&buf, g_buf);
    float* q    = buf;
    float* k    = q + QSZ;
    float* v    = k + QSZ;
    float* pk   = v + QSZ;
    float* pq   = pk + PSZ;
    float* vals = pq + PSZ;

    cudaFuncSetAttribute((const void*)flash_kernel,
                         cudaFuncAttributeMaxDynamicSharedMemorySize, FL_SMEM);

    // 1) Fused QKV projection (tf32 mma)
    mma_gemm<1><<<dim3(24, 12), 256>>>(x, Wq, Wk, Wv, bq, bk, bv, q, k, v, BB * SS, IND);

    // 2) Positional projections (767 distinct relative rows; rel rows 128..894)
    mma_gemm<2><<<dim3(6, 4), 256>>>(rel + 128 * IND, Wpk, nullptr, nullptr,
                                     bpk, nullptr, nullptr, pk, nullptr, nullptr, RR, IND);
    mma_gemm<2><<<dim3(6, 4), 256>>>(rel + 128 * IND, Wpq, nullptr, nullptr,
                                     bpq, nullptr, nullptr, pq, nullptr, nullptr, RR, IND);

    // 3) Fused flash attention (logits + softmax + A@V)
    flash_kernel<<<dim3(6, 64), 256, FL_SMEM>>>(q, k, v, pk, pq, mask, vals);

    // 4) Output projection
    mma_gemm<0><<<dim3(24, 4), 256>>>(vals, Wo, nullptr, nullptr,
                                      bo, nullptr, nullptr, out, nullptr, nullptr, BB * SS, EE);
}

// round 4
// speedup vs baseline: 3.1378x; 1.1992x over previous
#include <cuda_runtime.h>
#include <cstdint>

#define BB 8
#define SS 384
#define IND 512
#define EE 512
#define HH 8
#define DD 64
#define RR 767
#define SCALEF 0.07216878364870323f   // 1/sqrt(64*3)

#define QSZ (BB*HH*SS*DD)
#define PSZ (HH*RR*DD)
#define VSZ (BB*SS*EE)

__device__ float g_buf[3*QSZ + 2*PSZ + VSZ];

__device__ __forceinline__ uint32_t f2tf(float f) {
    uint32_t r;
    asm("cvt.rna.tf32.f32 %0, %1;" : "=r"(r) : "f"(f));
    return r;
}

__device__ __forceinline__ void mma_tf32(float c[4], uint32_t a0, uint32_t a1, uint32_t a2, uint32_t a3,
                                         uint32_t b0, uint32_t b1) {
    asm volatile("mma.sync.aligned.m16n8k8.row.col.f32.tf32.tf32.f32 "
                 "{%0,%1,%2,%3}, {%4,%5,%6,%7}, {%8,%9}, {%0,%1,%2,%3};"
                 : "+f"(c[0]), "+f"(c[1]), "+f"(c[2]), "+f"(c[3])
                 : "r"(a0), "r"(a1), "r"(a2), "r"(a3), "r"(b0), "r"(b1));
}

// ---------------------------------------------------------------------------
// Tensor-core GEMM: C[M,N] = A[M,K] @ W[N,K]^T + bias  (tf32 mma.sync)
// MODE 0: row-major C. MODE 1: fused QKV scatter [B,H,S,D].
// MODE 2: fused pos-k/pos-q projection (grid.y selects W0/W1), scatter [H,RR,D].
// ---------------------------------------------------------------------------
template<int MODE>
__launch_bounds__(256)
__global__ void mma_gemm(const float* __restrict__ A,
                         const float* __restrict__ W0, const float* __restrict__ W1, const float* __restrict__ W2,
                         const float* __restrict__ b0, const float* __restrict__ b1, const float* __restrict__ b2,
                         float* __restrict__ o0, float* __restrict__ o1, float* __restrict__ o2,
                         int M, int K)
{
    __shared__ uint32_t As[128][36];
    __shared__ uint32_t Ws[128][36];

    const int tid = threadIdx.x;
    const int m0 = blockIdx.x * 128;
    const int n0 = blockIdx.y * 128;

    const float* W = W0;
    const float* bias = b0;
    int which = 0;
    if (MODE == 1) {
        which = n0 >> 9;
        W    = (which == 0) ? W0 : (which == 1) ? W1 : W2;
        bias = (which == 0) ? b0 : (which == 1) ? b1 : b2;
    }
    if (MODE == 2) {
        which = n0 >> 9;
        W    = which ? W1 : W0;
        bias = which ? b1 : b0;
    }
    const int nW0 = (MODE == 0) ? n0 : (n0 & 511);

    const int w = tid >> 5;
    const int lane = tid & 31;
    const int g = lane >> 2;
    const int t = lane & 3;
    const int mrow = (w >> 2) * 64;
    const int wcol = (w & 3) * 32;

    const int srow = tid >> 3;
    const int skq  = (tid & 7) * 4;

    float acc[4][4][4];
#pragma unroll
    for (int mt = 0; mt < 4; mt++)
#pragma unroll
        for (int nt = 0; nt < 4; nt++)
#pragma unroll
            for (int i = 0; i < 4; i++) acc[mt][nt][i] = 0.f;

    for (int k0 = 0; k0 < K; k0 += 32) {
        if (k0) __syncthreads();
#pragma unroll
        for (int rr = 0; rr < 4; rr++) {
            const int row = rr * 32 + srow;
            float4 av = make_float4(0.f, 0.f, 0.f, 0.f);
            if (MODE != 2 || (m0 + row) < M)
                av = *(const float4*)(A + (size_t)(m0 + row) * K + k0 + skq);
            uint4 at;
            at.x = f2tf(av.x); at.y = f2tf(av.y); at.z = f2tf(av.z); at.w = f2tf(av.w);
            *(uint4*)&As[row][skq] = at;
            float4 wv = *(const float4*)(W + (size_t)(nW0 + row) * K + k0 + skq);
            uint4 wt;
            wt.x = f2tf(wv.x); wt.y = f2tf(wv.y); wt.z = f2tf(wv.z); wt.w = f2tf(wv.w);
            *(uint4*)&Ws[row][skq] = wt;
        }
        __syncthreads();

#pragma unroll
        for (int ks = 0; ks < 4; ks++) {
            const int kk = ks * 8;
            uint32_t a[4][4], bfr[4][2];
#pragma unroll
            for (int mt = 0; mt < 4; mt++) {
                const int r = mrow + mt * 16 + g;
                a[mt][0] = As[r][kk + t];
                a[mt][1] = As[r + 8][kk + t];
                a[mt][2] = As[r][kk + t + 4];
                a[mt][3] = As[r + 8][kk + t + 4];
            }
#pragma unroll
            for (int nt = 0; nt < 4; nt++) {
                const int r = wcol + nt * 8 + g;
                bfr[nt][0] = Ws[r][kk + t];
                bfr[nt][1] = Ws[r][kk + t + 4];
            }
#pragma unroll
            for (int mt = 0; mt < 4; mt++)
#pragma unroll
                for (int nt = 0; nt < 4; nt++)
                    mma_tf32(acc[mt][nt], a[mt][0], a[mt][1], a[mt][2], a[mt][3],
                             bfr[nt][0], bfr[nt][1]);
        }
    }

#pragma unroll
    for (int mt = 0; mt < 4; mt++) {
        const int rm0 = m0 + mrow + mt * 16 + g;
        const int rm1 = rm0 + 8;
#pragma unroll
        for (int nt = 0; nt < 4; nt++) {
            const int cn = wcol + nt * 8 + t * 2;
            const int n = n0 + cn;
            const float* cc = acc[mt][nt];
            if (MODE == 0) {
                const float bz0 = bias[n], bz1 = bias[n + 1];
                *(float2*)&o0[(size_t)rm0 * 512 + n] = make_float2(cc[0] + bz0, cc[1] + bz1);
                *(float2*)&o0[(size_t)rm1 * 512 + n] = make_float2(cc[2] + bz0, cc[3] + bz1);
            } else if (MODE == 1) {
                const int nn = n & 511;
                const float bz0 = bias[nn], bz1 = bias[nn + 1];
                float* o = (which == 0) ? o0 : (which == 1) ? o1 : o2;
                const int h = nn >> 6, d = nn & 63;
                {
                    const int b = rm0 / SS, s = rm0 % SS;
                    float* p = o + (((size_t)(b * HH + h)) * SS + s) * DD + d;
                    p[0] = cc[0] + bz0; p[1] = cc[1] + bz1;
                }
                {
                    const int b = rm1 / SS, s = rm1 % SS;
                    float* p = o + (((size_t)(b * HH + h)) * SS + s) * DD + d;
                    p[0] = cc[2] + bz0; p[1] = cc[3] + bz1;
                }
            } else {
                const int nn = n & 511;
                const float bz0 = bias[nn], bz1 = bias[nn + 1];
                float* o = which ? o1 : o0;
                const int h = nn >> 6, d = nn & 63;
                if (rm0 < M) {
                    float* p = o + ((size_t)h * RR + rm0) * DD + d;
                    p[0] = cc[0] + bz0; p[1] = cc[1] + bz1;
                }
                if (rm1 < M) {
                    float* p = o + ((size_t)h * RR + rm1) * DD + d;
                    p[0] = cc[2] + bz0; p[1] = cc[3] + bz1;
                }
            }
        }
    }
}

// ---------------------------------------------------------------------------
// Fused flash attention with disentangled relative-position terms.
// 512 threads, 16 warps in a 4(m) x 4(n) grid. One block per (bh, 64-row tile).
// ---------------------------------------------------------------------------
#define T64P 68
#define QPK_P 132
#define FL_U32 (4*64*T64P + 2*128*T64P + 608)
#define FL_SMEM (FL_U32 * 4)

__launch_bounds__(512, 1)
__global__ void flash_kernel(const float* __restrict__ gq, const float* __restrict__ gk,
                             const float* __restrict__ gv,
                             const float* __restrict__ gpk, const float* __restrict__ gpq,
                             const int* __restrict__ mask, float* __restrict__ vals)
{
    extern __shared__ uint32_t sm[];
    uint32_t* Qs = sm;
    uint32_t* Ks = sm + 64 * T64P;
    uint32_t* Vt = sm + 2 * 64 * T64P;
    uint32_t* Ps = sm + 3 * 64 * T64P;
    uint32_t* PKb = sm + 4 * 64 * T64P;        // [128][68] band; reused as QPKs [64][132] f32
    uint32_t* PQb = PKb + 128 * T64P;          // [128][68] band; reused as PQKs [128][68] f32
    float* QPKs = (float*)PKb;
    float* PQKs = (float*)PQb;
    float* maskb = (float*)(PQb + 128 * T64P); // [64]
    float* pm    = maskb + 64;                 // [4][64]
    float* psum  = pm + 256;                   // [4][64]

    const int bh = blockIdx.y;
    const int b = bh >> 3, h = bh & 7;
    const int i0 = blockIdx.x * 64;
    const int tid = threadIdx.x;
    const int w = tid >> 5, lane = tid & 31;
    const int g = lane >> 2, t = lane & 3;
    const int wm = w & 3, wn = w >> 2;        // 4 x 4 warp grid
    const int r0 = wm * 16 + g;               // S/O row slot 0 (slot 1 = r0+8)

    // ---- load Q tile (64x64) -> tf32 smem ----
    {
        const float* qb = gq + ((size_t)bh * SS + i0) * DD;
#pragma unroll
        for (int u = 0; u < 2; u++) {
            const int idx = tid + u * 512;
            const int r = idx & 63, c = (idx >> 6) * 4;
            float4 v = *(const float4*)(qb + r * DD + c);
            uint32_t* dst = &Qs[r * T64P + c];
            dst[0] = f2tf(v.x); dst[1] = f2tf(v.y); dst[2] = f2tf(v.z); dst[3] = f2tf(v.w);
        }
    }

    float oacc[2][4];
#pragma unroll
    for (int nt = 0; nt < 2; nt++)
#pragma unroll
        for (int i = 0; i < 4; i++) oacc[nt][i] = 0.f;
    float mrun[2] = {-INFINITY, -INFINITY};
    float lrun[2] = {0.f, 0.f};

    for (int j0 = 0; j0 < SS; j0 += 64) {
        // ---- stage K, V^T ----
        {
            const float* kb = gk + ((size_t)bh * SS + j0) * DD;
            const float* vb = gv + ((size_t)bh * SS + j0) * DD;
#pragma unroll
            for (int u = 0; u < 2; u++) {
                const int idx = tid + u * 512;
                const int r = idx & 63, c = (idx >> 6) * 4;
                float4 kv = *(const float4*)(kb + r * DD + c);
                uint32_t* dk = &Ks[r * T64P + c];
                dk[0] = f2tf(kv.x); dk[1] = f2tf(kv.y); dk[2] = f2tf(kv.z); dk[3] = f2tf(kv.w);
                float4 vv = *(const float4*)(vb + r * DD + c);
                Vt[(c + 0) * T64P + r] = f2tf(vv.x);
                Vt[(c + 1) * T64P + r] = f2tf(vv.y);
                Vt[(c + 2) * T64P + r] = f2tf(vv.z);
                Vt[(c + 3) * T64P + r] = f2tf(vv.w);
            }
        }
        // ---- stage bands ----
        {
            const int base_r = j0 - i0 + 320;
            const float* pkp = gpk + ((size_t)h * RR + base_r) * DD;
            const float* pqp = gpq + ((size_t)h * RR + base_r) * DD;
#pragma unroll
            for (int u = 0; u < 4; u++) {
                const int tt = tid + u * 512;
                const int r = tt >> 4, c = (tt & 15) * 4;
                float4 v = make_float4(0.f, 0.f, 0.f, 0.f);
                float4 u2 = make_float4(0.f, 0.f, 0.f, 0.f);
                if (r < 127) {
                    v = *(const float4*)(pkp + (size_t)r * DD + c);
                    u2 = *(const float4*)(pqp + (size_t)r * DD + c);
                }
                uint32_t* dp = &PKb[r * T64P + c];
                dp[0] = f2tf(v.x); dp[1] = f2tf(v.y); dp[2] = f2tf(v.z); dp[3] = f2tf(v.w);
                uint32_t* dq = &PQb[r * T64P + c];
                dq[0] = f2tf(u2.x); dq[1] = f2tf(u2.y); dq[2] = f2tf(u2.z); dq[3] = f2tf(u2.w);
            }
        }
        if (tid < 64) maskb[tid] = (mask[b * SS + j0 + tid] == 0) ? 0.f : 1.f;
        __syncthreads();

        // ---- MMAs: S (16x16/warp), QPK (16x32/warp), PQK (32x16/warp) ----
        float sacc[2][4];
        float qpk[4][4];
        float pqk[2][2][4];
#pragma unroll
        for (int nt = 0; nt < 2; nt++)
#pragma unroll
            for (int i = 0; i < 4; i++) sacc[nt][i] = 0.f;
#pragma unroll
        for (int nt = 0; nt < 4; nt++)
#pragma unroll
            for (int i = 0; i < 4; i++) qpk[nt][i] = 0.f;
#pragma unroll
        for (int mt = 0; mt < 2; mt++)
#pragma unroll
            for (int nt = 0; nt < 2; nt++)
#pragma unroll
                for (int i = 0; i < 4; i++) pqk[mt][nt][i] = 0.f;

#pragma unroll
        for (int ks = 0; ks < 8; ks++) {
            const int kk = ks * 8;
            uint32_t aq[4], apq[2][4], bk[2][2], bpk[4][2];
            aq[0] = Qs[r0 * T64P + kk + t];
            aq[1] = Qs[(r0 + 8) * T64P + kk + t];
            aq[2] = Qs[r0 * T64P + kk + t + 4];
            aq[3] = Qs[(r0 + 8) * T64P + kk + t + 4];
#pragma unroll
            for (int mt = 0; mt < 2; mt++) {
                const int rp = wm * 32 + mt * 16 + g;
                apq[mt][0] = PQb[rp * T64P + kk + t];
                apq[mt][1] = PQb[(rp + 8) * T64P + kk + t];
                apq[mt][2] = PQb[rp * T64P + kk + t + 4];
                apq[mt][3] = PQb[(rp + 8) * T64P + kk + t + 4];
            }
#pragma unroll
            for (int nt = 0; nt < 2; nt++) {
                const int rk = wn * 16 + nt * 8 + g;
                bk[nt][0] = Ks[rk * T64P + kk + t];
                bk[nt][1] = Ks[rk * T64P + kk + t + 4];
            }
#pragma unroll
            for (int nt = 0; nt < 4; nt++) {
                const int rb = wn * 32 + nt * 8 + g;
                bpk[nt][0] = PKb[rb * T64P + kk + t];
                bpk[nt][1] = PKb[rb * T64P + kk + t + 4];
            }
#pragma unroll
            for (int nt = 0; nt < 2; nt++)
                mma_tf32(sacc[nt], aq[0], aq[1], aq[2], aq[3], bk[nt][0], bk[nt][1]);
#pragma unroll
            for (int nt = 0; nt < 4; nt++)
                mma_tf32(qpk[nt], aq[0], aq[1], aq[2], aq[3], bpk[nt][0], bpk[nt][1]);
#pragma unroll
            for (int mt = 0; mt < 2; mt++)
#pragma unroll
                for (int nt = 0; nt < 2; nt++)
                    mma_tf32(pqk[mt][nt], apq[mt][0], apq[mt][1], apq[mt][2], apq[mt][3],
                             bk[nt][0], bk[nt][1]);
        }
        __syncthreads();   // bands consumed; safe to overwrite with gather results

        // ---- spill QPK/PQK (aliased over band buffers) ----
#pragma unroll
        for (int nt = 0; nt < 4; nt++) {
            const int cq = wn * 32 + nt * 8 + t * 2;
            QPKs[r0 * QPK_P + cq]           = qpk[nt][0];
            QPKs[r0 * QPK_P + cq + 1]       = qpk[nt][1];
            QPKs[(r0 + 8) * QPK_P + cq]     = qpk[nt][2];
            QPKs[(r0 + 8) * QPK_P + cq + 1] = qpk[nt][3];
        }
#pragma unroll
        for (int mt = 0; mt < 2; mt++) {
            const int rr = wm * 32 + mt * 16 + g;
#pragma unroll
            for (int nt = 0; nt < 2; nt++) {
                const int cl = wn * 16 + nt * 8 + t * 2;
                PQKs[rr * T64P + cl]           = pqk[mt][nt][0];
                PQKs[rr * T64P + cl + 1]       = pqk[mt][nt][1];
                PQKs[(rr + 8) * T64P + cl]     = pqk[mt][nt][2];
                PQKs[(rr + 8) * T64P + cl + 1] = pqk[mt][nt][3];
            }
        }
        __syncthreads();

        // ---- combine + mask + scale; per-warp partial row max ----
        float pvals[2][4];
        float tmax[2] = {-INFINITY, -INFINITY};
#pragma unroll
        for (int nt = 0; nt < 2; nt++) {
#pragma unroll
            for (int e = 0; e < 2; e++) {
                const int lj = wn * 16 + nt * 8 + t * 2 + e;
                const float mk = maskb[lj];
                const int t0 = lj - r0 + 63;
                float s0 = (sacc[nt][e] + QPKs[r0 * QPK_P + t0] + PQKs[t0 * T64P + lj]) * SCALEF;
                s0 = (mk != 0.f) ? s0 : -9.0e15f;
                const int t1 = t0 - 8;
                float s1 = (sacc[nt][2 + e] + QPKs[(r0 + 8) * QPK_P + t1] + PQKs[t1 * T64P + lj]) * SCALEF;
                s1 = (mk != 0.f) ? s1 : -9.0e15f;
                pvals[0][nt * 2 + e] = s0;
                pvals[1][nt * 2 + e] = s1;
                tmax[0] = fmaxf(tmax[0], s0);
                tmax[1] = fmaxf(tmax[1], s1);
            }
        }
#pragma unroll
        for (int r = 0; r < 2; r++) {
            tmax[r] = fmaxf(tmax[r], __shfl_xor_sync(0xffffffffu, tmax[r], 1));
            tmax[r] = fmaxf(tmax[r], __shfl_xor_sync(0xffffffffu, tmax[r], 2));
        }
        if (t == 0) { pm[wn * 64 + r0] = tmax[0]; pm[wn * 64 + r0 + 8] = tmax[1]; }
        __syncthreads();

        float mnew[2], alpha[2];
#pragma unroll
        for (int r = 0; r < 2; r++) {
            const int row = r0 + r * 8;
            float mt2 = fmaxf(fmaxf(pm[row], pm[64 + row]), fmaxf(pm[128 + row], pm[192 + row]));
            mnew[r] = fmaxf(mrun[r], mt2);
            alpha[r] = __expf(mrun[r] - mnew[r]);
            mrun[r] = mnew[r];
        }

        // ---- exp + partial row sums + write P (tf32) ----
        float tsum[2] = {0.f, 0.f};
#pragma unroll
        for (int q2 = 0; q2 < 4; q2++) {
            float p0 = __expf(pvals[0][q2] - mnew[0]);
            float p1 = __expf(pvals[1][q2] - mnew[1]);
            pvals[0][q2] = p0; pvals[1][q2] = p1;
            tsum[0] += p0; tsum[1] += p1;
        }
#pragma unroll
        for (int r = 0; r < 2; r++) {
            tsum[r] += __shfl_xor_sync(0xffffffffu, tsum[r], 1);
            tsum[r] += __shfl_xor_sync(0xffffffffu, tsum[r], 2);
        }
        if (t == 0) { psum[wn * 64 + r0] = tsum[0]; psum[wn * 64 + r0 + 8] = tsum[1]; }
#pragma unroll
        for (int nt = 0; nt < 2; nt++) {
            const int cb = wn * 16 + nt * 8 + t * 2;
            Ps[r0 * T64P + cb]           = f2tf(pvals[0][nt * 2]);
            Ps[r0 * T64P + cb + 1]       = f2tf(pvals[0][nt * 2 + 1]);
            Ps[(r0 + 8) * T64P + cb]     = f2tf(pvals[1][nt * 2]);
            Ps[(r0 + 8) * T64P + cb + 1] = f2tf(pvals[1][nt * 2 + 1]);
        }
        __syncthreads();

#pragma unroll
        for (int r = 0; r < 2; r++) {
            const int row = r0 + r * 8;
            lrun[r] = lrun[r] * alpha[r] + psum[row] + psum[64 + row] + psum[128 + row] + psum[192 + row];
        }
#pragma unroll
        for (int nt = 0; nt < 2; nt++) {
            oacc[nt][0] *= alpha[0]; oacc[nt][1] *= alpha[0];
            oacc[nt][2] *= alpha[1]; oacc[nt][3] *= alpha[1];
        }

        // ---- O += P @ V ----
#pragma unroll
        for (int ks = 0; ks < 8; ks++) {
            const int kk = ks * 8;
            uint32_t ap[4], bv2[2][2];
            ap[0] = Ps[r0 * T64P + kk + t];
            ap[1] = Ps[(r0 + 8) * T64P + kk + t];
            ap[2] = Ps[r0 * T64P + kk + t + 4];
            ap[3] = Ps[(r0 + 8) * T64P + kk + t + 4];
#pragma unroll
            for (int nt = 0; nt < 2; nt++) {
                const int rv = wn * 16 + nt * 8 + g;
                bv2[nt][0] = Vt[rv * T64P + kk + t];
                bv2[nt][1] = Vt[rv * T64P + kk + t + 4];
            }
#pragma unroll
            for (int nt = 0; nt < 2; nt++)
                mma_tf32(oacc[nt], ap[0], ap[1], ap[2], ap[3], bv2[nt][0], bv2[nt][1]);
        }
        __syncthreads();
    }

    // ---- finalize ----
    const float inv0 = 1.f / lrun[0];
    const float inv1 = 1.f / lrun[1];
    const int row0 = i0 + r0;
#pragma unroll
    for (int nt = 0; nt < 2; nt++) {
        const int d = wn * 16 + nt * 8 + t * 2;
        float* p0 = &vals[((size_t)(b * SS + row0)) * EE + h * 64 + d];
        *(float2*)p0 = make_float2(oacc[nt][0] * inv0, oacc[nt][1] * inv0);
        float* p1 = &vals[((size_t)(b * SS + row0 + 8)) * EE + h * 64 + d];
        *(float2*)p1 = make_float2(oacc[nt][2] * inv1, oacc[nt][3] * inv1);
    }
}

// ---------------------------------------------------------------------------
extern "C" void kernel_launch(void* const* d_in, const int* in_sizes, int n_in,
                              void* d_out, int out_size)
{
    const float* x    = (const float*)d_in[0];
    const int*   mask = (const int*)d_in[1];
    const float* Wq   = (const float*)d_in[2];
    const float* bq   = (const float*)d_in[3];
    const float* Wk   = (const float*)d_in[4];
    const float* bk   = (const float*)d_in[5];
    const float* Wv   = (const float*)d_in[6];
    const float* bv   = (const float*)d_in[7];
    const float* rel  = (const float*)d_in[8];
    const float* Wpk  = (const float*)d_in[9];
    const float* bpk  = (const float*)d_in[10];
    const float* Wpq  = (const float*)d_in[11];
    const float* bpq  = (const float*)d_in[12];
    const float* Wo   = (const float*)d_in[13];
    const float* bo   = (const float*)d_in[14];
    float* out = (float*)d_out;

    float* buf = nullptr;
    cudaGetSymbolAddress((void**)&buf, g_buf);
    float* q    = buf;
    float* k    = q + QSZ;
    float* v    = k + QSZ;
    float* pk   = v + QSZ;
    float* pq   = pk + PSZ;
    float* vals = pq + PSZ;

    cudaFuncSetAttribute((const void*)flash_kernel,
                         cudaFuncAttributeMaxDynamicSharedMemorySize, FL_SMEM);

    // 1) Fused QKV projection (tf32 mma)
    mma_gemm<1><<<dim3(24, 12), 256>>>(x, Wq, Wk, Wv, bq, bk, bv, q, k, v, BB * SS, IND);

    // 2) Merged positional projections (pk and pq in one launch; grid.y selects)
    mma_gemm<2><<<dim3(6, 8), 256>>>(rel + 128 * IND, Wpk, Wpq, nullptr,
                                     bpk, bpq, nullptr, pk, pq, nullptr, RR, IND);

    // 3) Fused flash attention (logits + softmax + A@V), 512 threads
    flash_kernel<<<dim3(6, 64), 512, FL_SMEM>>>(q, k, v, pk, pq, mask, vals);

    // 4) Output projection
    mma_gemm<0><<<dim3(24, 4), 256>>>(vals, Wo, nullptr, nullptr,
                                      bo, nullptr, nullptr, out, nullptr, nullptr, BB * SS, EE);
}